// round 1
// baseline (speedup 1.0000x reference)
#include <cuda_runtime.h>

// Problem constants (fixed by setup_inputs: audio (8, 80000) fp32)
#define BATCH   8
#define TLEN    80000
#define KFRM    250            // ceil(T/FRAME)
#define FRAME   320
#define LAGS    189            // ceil(16000/85)
#define LAG_MIN 5              // ceil(16000/3400)
#define HALFSZ  94             // LAGS // 2
#define SEGLEN  (FRAME + LAGS) // 509
#define NOUT    235            // median output length: K + PAD - WIN + 1
#define WINMED  30
#define PADM    14             // (WIN-1)//2
#define EPSF    1e-9f

// output layout (float32): f0[B*NOUT], whiten[B*NOUT], voiced[B*NOUT], energy[B*KFRM]
#define OFF_F0     0
#define OFF_WHITEN (BATCH * NOUT)
#define OFF_VOICED (2 * BATCH * NOUT)
#define OFF_ENERGY (3 * BATCH * NOUT)

__device__ int g_idx[BATCH * KFRM];   // scratch: per-frame best lag index

// ---------------------------------------------------------------------------
// Kernel 1: per-frame NCCF + argmax (with half-window preference) + energy.
// One CTA per (b,k) frame; 192 threads; lag t handled by thread t.
// Note: (EPS+n1)^2 is a positive per-frame constant -> irrelevant to the
// argmax and the 0.99 comparison, so we never compute it for NCCF.
// ---------------------------------------------------------------------------
__global__ void __launch_bounds__(192) nccf_kernel(const float* __restrict__ audio,
                                                   float* __restrict__ out) {
    const int blk = blockIdx.x;           // b*KFRM + k
    const int b   = blk / KFRM;
    const int k   = blk - b * KFRM;
    const int tid = threadIdx.x;

    __shared__ __align__(16) float seg[SEGLEN + 3];  // pad to 512
    __shared__ float sval[192];
    __shared__ float sred[192];

    // Stage segment (zero-padded past T, matching jnp.pad)
    const float* row  = audio + (size_t)b * TLEN;
    const int    base = k * FRAME;
    for (int j = tid; j < SEGLEN + 3; j += 192) {
        float v = 0.0f;
        if (j < SEGLEN && base + j < TLEN) v = row[base + j];
        seg[j] = v;
    }
    __syncthreads();

    // Energy partial: sum of s1^2 (s1 = seg[0..FRAME))
    float e = 0.0f;
    for (int i = tid; i < FRAME; i += 192) e += seg[i] * seg[i];
    sred[tid] = e;

    // Per-lag cross-correlation + norm2
    float v = -3.0e38f;
    if (tid < LAGS) {
        const float* p = seg + tid + 1;
        float c = 0.0f, n = 0.0f;
        #pragma unroll 8
        for (int i = 0; i < FRAME; i += 4) {
            float4 a = *reinterpret_cast<const float4*>(&seg[i]);  // broadcast LDS.128
            float x0 = p[i], x1 = p[i + 1], x2 = p[i + 2], x3 = p[i + 3];
            c = fmaf(a.x, x0, c); c = fmaf(a.y, x1, c);
            c = fmaf(a.z, x2, c); c = fmaf(a.w, x3, c);
            n = fmaf(x0, x0, n);  n = fmaf(x1, x1, n);
            n = fmaf(x2, x2, n);  n = fmaf(x3, x3, n);
        }
        float d = EPSF + sqrtf(n);
        v = c / (d * d);
    }
    sval[tid] = v;
    __syncthreads();

    const int wid  = tid >> 5;
    const int lane = tid & 31;

    if (wid == 0) {
        // First-occurrence argmax over tail [LAG_MIN, LAGS) and half [LAG_MIN, HALFSZ)
        float bv = -3.0e38f; int bi = 1 << 30;
        float hv = -3.0e38f; int hi = 1 << 30;
        for (int t = LAG_MIN + lane; t < LAGS; t += 32) {
            float x = sval[t];
            if (x > bv) { bv = x; bi = t; }
            if (t < HALFSZ && x > hv) { hv = x; hi = t; }
        }
        #pragma unroll
        for (int off = 16; off; off >>= 1) {
            float ov  = __shfl_down_sync(0xffffffffu, bv, off);
            int   oi  = __shfl_down_sync(0xffffffffu, bi, off);
            if (ov > bv || (ov == bv && oi < bi)) { bv = ov; bi = oi; }
            float ohv = __shfl_down_sync(0xffffffffu, hv, off);
            int   ohi = __shfl_down_sync(0xffffffffu, hi, off);
            if (ohv > hv || (ohv == hv && ohi < hi)) { hv = ohv; hi = ohi; }
        }
        if (lane == 0) {
            int sel = (hv > 0.99f * bv) ? hi : bi;
            g_idx[blk] = sel + 1;   // (slice_i + LAG_MIN + 1) == lag_index + 1
        }
    } else if (wid == 1) {
        // Energy reduction
        float s = 0.0f;
        for (int t = lane; t < 192; t += 32) s += sred[t];
        #pragma unroll
        for (int off = 16; off; off >>= 1) s += __shfl_down_sync(0xffffffffu, s, off);
        if (lane == 0) out[OFF_ENERGY + blk] = s * (1.0f / FRAME);
    }
}

// ---------------------------------------------------------------------------
// Kernel 2: sliding lower-median (rank 14 of 30) with left replicate pad,
// then f0 = SR/(eps+idx) and voiced = 1. One CTA per batch row.
// Selection via binary search over the small int value range (no dynamic
// register indexing -> no local spills).
// ---------------------------------------------------------------------------
__global__ void __launch_bounds__(256) median_kernel(float* __restrict__ out) {
    const int b = blockIdx.x;
    __shared__ int row[KFRM];
    for (int t = threadIdx.x; t < KFRM; t += 256) row[t] = g_idx[b * KFRM + t];
    __syncthreads();

    const int j = threadIdx.x;
    if (j < NOUT) {
        int w[WINMED];
        #pragma unroll
        for (int m = 0; m < WINMED; m++) {
            int p = j + m - PADM;
            w[m] = row[p < 0 ? 0 : p];
        }
        // rank-14 (0-based) element = smallest x with count(w <= x) >= 15
        int lo = 1, hi = LAGS + 1;
        #pragma unroll
        for (int it = 0; it < 8; it++) {
            if (lo >= hi) break;
            int mid = (lo + hi) >> 1;
            int cnt = 0;
            #pragma unroll
            for (int m = 0; m < WINMED; m++) cnt += (w[m] <= mid);
            if (cnt >= PADM + 1) hi = mid; else lo = mid + 1;
        }
        float f0 = 16000.0f / (1e-9f + (float)lo);
        out[OFF_F0 + b * NOUT + j]     = f0;
        out[OFF_VOICED + b * NOUT + j] = 1.0f;   // f0 > 0 always (idx >= 6)
    }
}

// ---------------------------------------------------------------------------
// Kernel 3: global mean/std over all f0 (two-pass, matches reference
// formulation), write whiten. Single block.
// ---------------------------------------------------------------------------
__global__ void __launch_bounds__(512) stats_kernel(float* __restrict__ out) {
    const int N = BATCH * NOUT;   // 1880
    __shared__ float red[512];
    const int tid = threadIdx.x;

    float s = 0.0f;
    for (int i = tid; i < N; i += 512) s += out[OFF_F0 + i];
    red[tid] = s;
    __syncthreads();
    #pragma unroll
    for (int off = 256; off; off >>= 1) {
        if (tid < off) red[tid] += red[tid + off];
        __syncthreads();
    }
    float mean = red[0] / (float)N;
    __syncthreads();

    float s2 = 0.0f;
    for (int i = tid; i < N; i += 512) {
        float d = out[OFF_F0 + i] - mean;
        s2 = fmaf(d, d, s2);
    }
    red[tid] = s2;
    __syncthreads();
    #pragma unroll
    for (int off = 256; off; off >>= 1) {
        if (tid < off) red[tid] += red[tid + off];
        __syncthreads();
    }
    float var = red[0] / (float)(N - 1);
    float sd  = sqrtf(var);
    if (sd == 0.0f) sd = 1.0f;
    float inv = 1.0f / sd;

    for (int i = tid; i < N; i += 512)
        out[OFF_WHITEN + i] = (out[OFF_F0 + i] - mean) * inv;
}

extern "C" void kernel_launch(void* const* d_in, const int* in_sizes, int n_in,
                              void* d_out, int out_size) {
    const float* audio = (const float*)d_in[0];
    float* out = (float*)d_out;
    (void)in_sizes; (void)n_in; (void)out_size;

    nccf_kernel<<<BATCH * KFRM, 192>>>(audio, out);
    median_kernel<<<BATCH, 256>>>(out);
    stats_kernel<<<1, 512>>>(out);
}

// round 2
// speedup vs baseline: 1.3220x; 1.3220x over previous
#include <cuda_runtime.h>

// Problem constants (fixed by setup_inputs: audio (8, 80000) fp32)
#define BATCH   8
#define TLEN    80000
#define KFRM    250
#define FRAME   320
#define LAGS    189
#define LAG_MIN 5
#define HALFSZ  94             // LAGS // 2
#define SEGLEN  509            // FRAME + LAGS
#define NOUT    235
#define WINMED  30
#define PADM    14
#define EPSF    1e-9f

// nccf kernel blocking
#define LPT   8                // lags per thread
#define TPF   24               // threads per frame (192 lags padded)
#define FPB   4                // frames per block
#define NLAGP 192
#define SEGL  520              // logical padded segment length
#define SEGP  584              // physical (skewed) words per frame: skew(519)=583

// output layout (float32): f0[B*NOUT], whiten[B*NOUT], voiced[B*NOUT], energy[B*KFRM]
#define OFF_F0     0
#define OFF_WHITEN (BATCH * NOUT)
#define OFF_VOICED (2 * BATCH * NOUT)
#define OFF_ENERGY (3 * BATCH * NOUT)

__device__ int g_idx[BATCH * KFRM];
__device__ unsigned int g_ctr;

typedef unsigned long long ull;

__device__ __forceinline__ int skew(int m) { return m + ((m >> 5) << 2); }

__device__ __forceinline__ ull pk(float lo, float hi) {
    ull r; asm("mov.b64 %0, {%1, %2};" : "=l"(r) : "f"(lo), "f"(hi)); return r;
}
__device__ __forceinline__ void upk(float& lo, float& hi, ull v) {
    asm("mov.b64 {%0, %1}, %2;" : "=f"(lo), "=f"(hi) : "l"(v));
}
__device__ __forceinline__ void ffma2(ull& d, ull a, ull b) {
    asm("fma.rn.f32x2 %0, %1, %2, %0;" : "+l"(d) : "l"(a), "l"(b));
}

// ---------------------------------------------------------------------------
// Kernel 1: NCCF + argmax + energy. 4 frames/block, 128 threads.
// Compute: 96 threads, thread g of frame f handles lags 8g..8g+7 with a
// sliding register window; packed f32x2 FMAs; norms via running sum + fixups.
// Argmax: warp w handles frame w (first-occurrence semantics preserved).
// ---------------------------------------------------------------------------
__global__ void __launch_bounds__(128) nccf_kernel(const float* __restrict__ audio,
                                                   float* __restrict__ out) {
    __shared__ __align__(16) float seg[FPB][SEGP];
    __shared__ float sval[FPB][NLAGP];

    const int tid  = threadIdx.x;
    const int warp = tid >> 5;
    const int lane = tid & 31;
    const int fr0  = blockIdx.x * FPB;

    if (blockIdx.x == 0 && tid == 0) g_ctr = 0;  // reset for fused kernel 2

    // Stage: warp w stages frame w (skewed layout, zero-padded)
    {
        const int fr = fr0 + warp;
        const int b  = fr / KFRM;
        const int k  = fr - b * KFRM;
        const float* row  = audio + (size_t)b * TLEN;
        const int    base = k * FRAME;
        for (int j = lane; j < SEGL; j += 32) {
            float v = 0.0f;
            if (j < SEGLEN && base + j < TLEN) v = row[base + j];
            seg[warp][skew(j)] = v;
        }
    }
    __syncthreads();

    if (tid < FPB * TPF) {
        const int f = tid / TPF;
        const int g = tid - f * TPF;
        const float* sf = seg[f];
        const int gb = 8 * g;

        ull c0 = 0, c1 = 0, c2 = 0, c3 = 0, c4 = 0, c5 = 0, c6 = 0, c7 = 0, ns = 0;
        // window pairs over y_j = seg[8g + 4s + j]
        float4 W1;
        ull O0, O1, O2, E1, E2, E3;
        {
            float4 W0 = *reinterpret_cast<const float4*>(sf + skew(gb));
            W1        = *reinterpret_cast<const float4*>(sf + skew(gb + 4));
            O0 = pk(W0.y, W0.z); O1 = pk(W0.w, W1.x); O2 = pk(W1.y, W1.z);
            E1 = pk(W0.z, W0.w); E2 = pk(W1.x, W1.y); E3 = pk(W1.z, W1.w);
        }

        #pragma unroll 4
        for (int s = 0; s < 80; s++) {
            const float* ap = sf + skew(4 * s);
            ull A01 = *reinterpret_cast<const ull*>(ap);       // broadcast LDS.64
            ull A23 = *reinterpret_cast<const ull*>(ap + 2);
            float4 W2 = *reinterpret_cast<const float4*>(sf + skew(gb + 8 + 4 * s));

            ull O3 = pk(W1.w, W2.x);
            ull E4 = pk(W2.x, W2.y);
            ull O4 = pk(W2.y, W2.z);
            ull E5 = pk(W2.z, W2.w);

            ffma2(c0, A01, O0); ffma2(c0, A23, O1);
            ffma2(c1, A01, E1); ffma2(c1, A23, E2);
            ffma2(c2, A01, O1); ffma2(c2, A23, O2);
            ffma2(c3, A01, E2); ffma2(c3, A23, E3);
            ffma2(c4, A01, O2); ffma2(c4, A23, O3);
            ffma2(c5, A01, E3); ffma2(c5, A23, E4);
            ffma2(c6, A01, O3); ffma2(c6, A23, O4);
            ffma2(c7, A01, E4); ffma2(c7, A23, E5);
            ffma2(ns, O0, O0);  ffma2(ns, O1, O1);

            O0 = O2; O1 = O3; O2 = O4;
            E1 = E3; E2 = E4; E3 = E5;
            W1 = W2;
        }

        // norms: n2[0] from running sum, n2[l] via endpoint fixups
        float n2[8];
        { float lo, hi; upk(lo, hi, ns); n2[0] = lo + hi; }
        #pragma unroll
        for (int l = 1; l < 8; l++) {
            float xa = sf[skew(gb + l)];
            float xb = sf[skew(gb + 320 + l)];
            n2[l] = n2[l - 1] - xa * xa + xb * xb;
        }
        float cr[8];
        { float lo, hi;
          upk(lo, hi, c0); cr[0] = lo + hi; upk(lo, hi, c1); cr[1] = lo + hi;
          upk(lo, hi, c2); cr[2] = lo + hi; upk(lo, hi, c3); cr[3] = lo + hi;
          upk(lo, hi, c4); cr[4] = lo + hi; upk(lo, hi, c5); cr[5] = lo + hi;
          upk(lo, hi, c6); cr[6] = lo + hi; upk(lo, hi, c7); cr[7] = lo + hi; }
        #pragma unroll
        for (int l = 0; l < 8; l++) {
            float d = EPSF + sqrtf(n2[l]);
            sval[f][gb + l] = cr[l] / (d * d);
        }

        if (g == 0) {  // energy = mean(s1^2) = (n2[0] + seg[0]^2 - seg[320]^2)/320
            float x0 = sf[skew(0)], x3 = sf[skew(320)];
            out[OFF_ENERGY + fr0 + f] = (n2[0] + x0 * x0 - x3 * x3) * (1.0f / FRAME);
        }
    }
    __syncthreads();

    // Argmax per frame: warp w scans sval[w][LAG_MIN..LAGS)
    {
        const float* sv = sval[warp];
        float bv = -3.0e38f; int bi = 1 << 30;
        float hv = -3.0e38f; int hi = 1 << 30;
        for (int t = LAG_MIN + lane; t < LAGS; t += 32) {
            float x = sv[t];
            if (x > bv) { bv = x; bi = t; }
            if (t < HALFSZ && x > hv) { hv = x; hi = t; }
        }
        #pragma unroll
        for (int off = 16; off; off >>= 1) {
            float ov  = __shfl_down_sync(0xffffffffu, bv, off);
            int   oi  = __shfl_down_sync(0xffffffffu, bi, off);
            if (ov > bv || (ov == bv && oi < bi)) { bv = ov; bi = oi; }
            float ohv = __shfl_down_sync(0xffffffffu, hv, off);
            int   ohi = __shfl_down_sync(0xffffffffu, hi, off);
            if (ohv > hv || (ohv == hv && ohi < hi)) { hv = ohv; hi = ohi; }
        }
        if (lane == 0) {
            int sel = (hv > 0.99f * bv) ? hi : bi;
            g_idx[fr0 + warp] = sel + 1;
        }
    }
}

// ---------------------------------------------------------------------------
// Kernel 2 (fused): sliding lower-median -> f0/voiced per batch row (8 blocks),
// then the last block to finish computes global mean/std and writes whiten.
// ---------------------------------------------------------------------------
__global__ void __launch_bounds__(256) median_stats_kernel(float* __restrict__ out) {
    const int b = blockIdx.x;
    __shared__ int   row[KFRM];
    __shared__ float red[256];
    __shared__ bool  s_last;

    for (int t = threadIdx.x; t < KFRM; t += 256) row[t] = g_idx[b * KFRM + t];
    __syncthreads();

    const int j = threadIdx.x;
    if (j < NOUT) {
        int w[WINMED];
        #pragma unroll
        for (int m = 0; m < WINMED; m++) {
            int p = j + m - PADM;
            w[m] = row[p < 0 ? 0 : p];
        }
        int lo = 1, hi = LAGS + 1;
        #pragma unroll
        for (int it = 0; it < 8; it++) {
            if (lo >= hi) break;
            int mid = (lo + hi) >> 1;
            int cnt = 0;
            #pragma unroll
            for (int m = 0; m < WINMED; m++) cnt += (w[m] <= mid);
            if (cnt >= PADM + 1) hi = mid; else lo = mid + 1;
        }
        float f0 = 16000.0f / (1e-9f + (float)lo);
        out[OFF_F0 + b * NOUT + j]     = f0;
        out[OFF_VOICED + b * NOUT + j] = 1.0f;
    }
    __threadfence();
    __syncthreads();
    if (threadIdx.x == 0) s_last = (atomicAdd(&g_ctr, 1u) == BATCH - 1);
    __syncthreads();
    if (!s_last) return;
    __threadfence();

    // Stats over all f0 (two-pass, matches reference formulation)
    const int N = BATCH * NOUT;  // 1880
    const int tid = threadIdx.x;
    float s = 0.0f;
    for (int i = tid; i < N; i += 256) s += out[OFF_F0 + i];
    red[tid] = s;
    __syncthreads();
    #pragma unroll
    for (int off = 128; off; off >>= 1) {
        if (tid < off) red[tid] += red[tid + off];
        __syncthreads();
    }
    float mean = red[0] / (float)N;
    __syncthreads();

    float s2 = 0.0f;
    for (int i = tid; i < N; i += 256) {
        float d = out[OFF_F0 + i] - mean;
        s2 = fmaf(d, d, s2);
    }
    red[tid] = s2;
    __syncthreads();
    #pragma unroll
    for (int off = 128; off; off >>= 1) {
        if (tid < off) red[tid] += red[tid + off];
        __syncthreads();
    }
    float sd = sqrtf(red[0] / (float)(N - 1));
    if (sd == 0.0f) sd = 1.0f;
    float inv = 1.0f / sd;
    for (int i = tid; i < N; i += 256)
        out[OFF_WHITEN + i] = (out[OFF_F0 + i] - mean) * inv;
}

extern "C" void kernel_launch(void* const* d_in, const int* in_sizes, int n_in,
                              void* d_out, int out_size) {
    const float* audio = (const float*)d_in[0];
    float* out = (float*)d_out;
    (void)in_sizes; (void)n_in; (void)out_size;

    nccf_kernel<<<(BATCH * KFRM) / FPB, 128>>>(audio, out);
    median_stats_kernel<<<BATCH, 256>>>(out);
}

// round 3
// speedup vs baseline: 1.3253x; 1.0025x over previous
#include <cuda_runtime.h>

// Problem constants (fixed by setup_inputs: audio (8, 80000) fp32)
#define BATCH   8
#define TLEN    80000
#define KFRM    250
#define FRAME   320
#define LAGS    189
#define LAG_MIN 5
#define HALFSZ  94             // LAGS // 2
#define SEGLEN  509            // FRAME + LAGS
#define NOUT    235
#define WINMED  30
#define PADM    14
#define EPSF    1e-9f

// nccf kernel blocking
#define LPT   8                // lags per thread
#define TPF   24               // threads per frame (192 lags padded)
#define FPB   4                // frames per block
#define NWARP 3                // warps per block (96 threads)
#define NLAGP 192
#define SEGL  520              // logical padded segment length
#define SEGP  584              // physical (skewed) words per frame

// output layout (float32): f0[B*NOUT], whiten[B*NOUT], voiced[B*NOUT], energy[B*KFRM]
#define OFF_F0     0
#define OFF_WHITEN (BATCH * NOUT)
#define OFF_VOICED (2 * BATCH * NOUT)
#define OFF_ENERGY (3 * BATCH * NOUT)

__device__ int g_idx[BATCH * KFRM];

typedef unsigned long long ull;

__device__ __forceinline__ int skew(int m) { return m + ((m >> 5) << 2); }

__device__ __forceinline__ ull pk(float lo, float hi) {
    ull r; asm("mov.b64 %0, {%1, %2};" : "=l"(r) : "f"(lo), "f"(hi)); return r;
}
__device__ __forceinline__ void upk(float& lo, float& hi, ull v) {
    asm("mov.b64 {%0, %1}, %2;" : "=f"(lo), "=f"(hi) : "l"(v));
}
__device__ __forceinline__ void ffma2(ull& d, ull a, ull b) {
    asm("fma.rn.f32x2 %0, %1, %2, %0;" : "+l"(d) : "l"(a), "l"(b));
}

// ---------------------------------------------------------------------------
// Kernel 1: NCCF + argmax + energy. 4 frames/block, 96 threads (all compute).
// Thread g of frame f handles lags 8g..8g+7 via a sliding register window;
// packed f32x2 FMAs; per-lag norms from one running sum + endpoint fixups.
// ---------------------------------------------------------------------------
__global__ void __launch_bounds__(96) nccf_kernel(const float* __restrict__ audio,
                                                  float* __restrict__ out) {
    __shared__ __align__(16) float seg[FPB][SEGP];
    __shared__ float sval[FPB][NLAGP];

    const int tid  = threadIdx.x;
    const int warp = tid >> 5;
    const int lane = tid & 31;
    const int fr0  = blockIdx.x * FPB;

    // Stage: 3 warps stage 4 frames (skewed layout, zero-padded)
    for (int fr = warp; fr < FPB; fr += NWARP) {
        const int gfr = fr0 + fr;
        const int b   = gfr / KFRM;
        const int k   = gfr - b * KFRM;
        const float* row  = audio + (size_t)b * TLEN;
        const int    base = k * FRAME;
        for (int j = lane; j < SEGL; j += 32) {
            float v = 0.0f;
            if (j < SEGLEN && base + j < TLEN) v = row[base + j];
            seg[fr][skew(j)] = v;
        }
    }
    __syncthreads();

    {
        const int f = tid / TPF;
        const int g = tid - f * TPF;
        const float* sf = seg[f];
        const int gb = 8 * g;

        ull c0 = 0, c1 = 0, c2 = 0, c3 = 0, c4 = 0, c5 = 0, c6 = 0, c7 = 0, ns = 0;
        float4 W1;
        ull O0, O1, O2, E1, E2, E3;
        {
            float4 W0 = *reinterpret_cast<const float4*>(sf + skew(gb));
            W1        = *reinterpret_cast<const float4*>(sf + skew(gb + 4));
            O0 = pk(W0.y, W0.z); O1 = pk(W0.w, W1.x); O2 = pk(W1.y, W1.z);
            E1 = pk(W0.z, W0.w); E2 = pk(W1.x, W1.y); E3 = pk(W1.z, W1.w);
        }

        #pragma unroll 4
        for (int s = 0; s < 80; s++) {
            float4 Aq = *reinterpret_cast<const float4*>(sf + skew(4 * s)); // broadcast LDS.128
            ull A01 = pk(Aq.x, Aq.y);
            ull A23 = pk(Aq.z, Aq.w);
            float4 W2 = *reinterpret_cast<const float4*>(sf + skew(gb + 8 + 4 * s));

            ull O3 = pk(W1.w, W2.x);
            ull E4 = pk(W2.x, W2.y);
            ull O4 = pk(W2.y, W2.z);
            ull E5 = pk(W2.z, W2.w);

            ffma2(c0, A01, O0); ffma2(c0, A23, O1);
            ffma2(c1, A01, E1); ffma2(c1, A23, E2);
            ffma2(c2, A01, O1); ffma2(c2, A23, O2);
            ffma2(c3, A01, E2); ffma2(c3, A23, E3);
            ffma2(c4, A01, O2); ffma2(c4, A23, O3);
            ffma2(c5, A01, E3); ffma2(c5, A23, E4);
            ffma2(c6, A01, O3); ffma2(c6, A23, O4);
            ffma2(c7, A01, E4); ffma2(c7, A23, E5);
            ffma2(ns, O0, O0);  ffma2(ns, O1, O1);

            O0 = O2; O1 = O3; O2 = O4;
            E1 = E3; E2 = E4; E3 = E5;
            W1 = W2;
        }

        // norms: n2[0] from running sum, n2[l] via endpoint fixups
        float n2[8];
        { float lo, hi; upk(lo, hi, ns); n2[0] = lo + hi; }
        #pragma unroll
        for (int l = 1; l < 8; l++) {
            float xa = sf[skew(gb + l)];
            float xb = sf[skew(gb + 320 + l)];
            n2[l] = n2[l - 1] - xa * xa + xb * xb;
        }
        float cr[8];
        { float lo, hi;
          upk(lo, hi, c0); cr[0] = lo + hi; upk(lo, hi, c1); cr[1] = lo + hi;
          upk(lo, hi, c2); cr[2] = lo + hi; upk(lo, hi, c3); cr[3] = lo + hi;
          upk(lo, hi, c4); cr[4] = lo + hi; upk(lo, hi, c5); cr[5] = lo + hi;
          upk(lo, hi, c6); cr[6] = lo + hi; upk(lo, hi, c7); cr[7] = lo + hi; }
        #pragma unroll
        for (int l = 0; l < 8; l++) {
            float d = EPSF + sqrtf(n2[l]);
            sval[f][gb + l] = cr[l] / (d * d);
        }

        if (g == 0) {  // energy = mean(s1^2) = (n2[0] + seg[0]^2 - seg[320]^2)/320
            float x0 = sf[skew(0)], x3 = sf[skew(320)];
            out[OFF_ENERGY + fr0 + f] = (n2[0] + x0 * x0 - x3 * x3) * (1.0f / FRAME);
        }
    }
    __syncthreads();

    // Argmax per frame: 3 warps cover 4 frames (first-occurrence semantics)
    for (int fr = warp; fr < FPB; fr += NWARP) {
        const float* sv = sval[fr];
        float bv = -3.0e38f; int bi = 1 << 30;
        float hv = -3.0e38f; int hi = 1 << 30;
        for (int t = LAG_MIN + lane; t < LAGS; t += 32) {
            float x = sv[t];
            if (x > bv) { bv = x; bi = t; }
            if (t < HALFSZ && x > hv) { hv = x; hi = t; }
        }
        #pragma unroll
        for (int off = 16; off; off >>= 1) {
            float ov  = __shfl_down_sync(0xffffffffu, bv, off);
            int   oi  = __shfl_down_sync(0xffffffffu, bi, off);
            if (ov > bv || (ov == bv && oi < bi)) { bv = ov; bi = oi; }
            float ohv = __shfl_down_sync(0xffffffffu, hv, off);
            int   ohi = __shfl_down_sync(0xffffffffu, hi, off);
            if (ohv > hv || (ohv == hv && ohi < hi)) { hv = ohv; hi = ohi; }
        }
        if (lane == 0) {
            int sel = (hv > 0.99f * bv) ? hi : bi;
            g_idx[fr0 + fr] = sel + 1;
        }
    }
}

// ---------------------------------------------------------------------------
// Kernel 2: sliding lower-median (rank 14 of 30) with left replicate pad,
// then f0 = SR/(eps+idx), voiced = 1. One CTA per batch row.
// ---------------------------------------------------------------------------
__global__ void __launch_bounds__(256) median_kernel(float* __restrict__ out) {
    const int b = blockIdx.x;
    __shared__ int row[KFRM];
    for (int t = threadIdx.x; t < KFRM; t += 256) row[t] = g_idx[b * KFRM + t];
    __syncthreads();

    const int j = threadIdx.x;
    if (j < NOUT) {
        int w[WINMED];
        #pragma unroll
        for (int m = 0; m < WINMED; m++) {
            int p = j + m - PADM;
            w[m] = row[p < 0 ? 0 : p];
        }
        // rank-14 (0-based) = smallest x with count(w <= x) >= 15
        int lo = 1, hi = LAGS + 1;
        #pragma unroll
        for (int it = 0; it < 8; it++) {
            int mid = (lo + hi) >> 1;
            int cnt = 0;
            #pragma unroll
            for (int m = 0; m < WINMED; m++) cnt += (w[m] <= mid);
            if (cnt >= PADM + 1) hi = mid; else lo = (lo < hi) ? mid + 1 : lo;
            if (lo > hi) hi = lo;
        }
        float f0 = 16000.0f / (1e-9f + (float)lo);
        out[OFF_F0 + b * NOUT + j]     = f0;
        out[OFF_VOICED + b * NOUT + j] = 1.0f;   // idx >= 6 -> f0 > 0 always
    }
}

// ---------------------------------------------------------------------------
// Kernel 3: global mean/std over all f0 (two-pass, matches reference), whiten.
// ---------------------------------------------------------------------------
__global__ void __launch_bounds__(512) stats_kernel(float* __restrict__ out) {
    const int N = BATCH * NOUT;   // 1880
    __shared__ float red[512];
    __shared__ float f0s[BATCH * NOUT];
    const int tid = threadIdx.x;

    float s = 0.0f;
    for (int i = tid; i < N; i += 512) {
        float v = out[OFF_F0 + i];
        f0s[i] = v;
        s += v;
    }
    red[tid] = s;
    __syncthreads();
    #pragma unroll
    for (int off = 256; off; off >>= 1) {
        if (tid < off) red[tid] += red[tid + off];
        __syncthreads();
    }
    float mean = red[0] / (float)N;
    __syncthreads();

    float s2 = 0.0f;
    for (int i = tid; i < N; i += 512) {
        float d = f0s[i] - mean;
        s2 = fmaf(d, d, s2);
    }
    red[tid] = s2;
    __syncthreads();
    #pragma unroll
    for (int off = 256; off; off >>= 1) {
        if (tid < off) red[tid] += red[tid + off];
        __syncthreads();
    }
    float sd = sqrtf(red[0] / (float)(N - 1));
    if (sd == 0.0f) sd = 1.0f;
    float inv = 1.0f / sd;

    for (int i = tid; i < N; i += 512)
        out[OFF_WHITEN + i] = (f0s[i] - mean) * inv;
}

extern "C" void kernel_launch(void* const* d_in, const int* in_sizes, int n_in,
                              void* d_out, int out_size) {
    const float* audio = (const float*)d_in[0];
    float* out = (float*)d_out;
    (void)in_sizes; (void)n_in; (void)out_size;

    nccf_kernel<<<(BATCH * KFRM) / FPB, FPB * TPF>>>(audio, out);
    median_kernel<<<BATCH, 256>>>(out);
    stats_kernel<<<1, 512>>>(out);
}